// round 2
// baseline (speedup 1.0000x reference)
#include <cuda_runtime.h>
#include <cstdint>

#define N_NODES  50000
#define N_EDGES  1600000
#define IN_FEAT  256
#define HID      128
#define OUT_FEAT 256
#define K_TOT    (2 * IN_FEAT)   // 512: concat [x | msg]

// Scratch (device globals: no allocations allowed in kernel_launch)
__device__ float4 g_msg[N_NODES * (IN_FEAT / 4)];   // 50000 x 256 fp32 = 51.2 MB
__device__ float  g_A2[K_TOT * OUT_FEAT];           // folded weights [512 x 256]
__device__ float  g_c[OUT_FEAT];                    // folded bias

// ---------------------------------------------------------------------------
// 0) zero the message accumulator (must be re-zeroed every graph replay)
// ---------------------------------------------------------------------------
__global__ void zero_msg_kernel() {
    int total = N_NODES * (IN_FEAT / 4);
    for (int i = blockIdx.x * blockDim.x + threadIdx.x; i < total;
         i += gridDim.x * blockDim.x) {
        g_msg[i] = make_float4(0.f, 0.f, 0.f, 0.f);
    }
}

// ---------------------------------------------------------------------------
// 1) fold weights:  A2[k,n] = (k<256 ? W_node[k,:] : W_edge[k-256,:]) . W_mlp[:,n]
//    c[n] = (b_node+b_edge) . W_mlp[:,n] + b_mlp[n]
// ---------------------------------------------------------------------------
__global__ void fold_weights_kernel(const float* __restrict__ Wn,
                                    const float* __restrict__ bn,
                                    const float* __restrict__ We,
                                    const float* __restrict__ be,
                                    const float* __restrict__ Wm,
                                    const float* __restrict__ bm) {
    int idx = blockIdx.x * blockDim.x + threadIdx.x;
    if (idx < K_TOT * OUT_FEAT) {
        int k = idx / OUT_FEAT;
        int n = idx % OUT_FEAT;
        const float* wrow = (k < IN_FEAT) ? (Wn + (size_t)k * HID)
                                          : (We + (size_t)(k - IN_FEAT) * HID);
        float acc = 0.f;
        #pragma unroll 4
        for (int j = 0; j < HID; ++j)
            acc = fmaf(wrow[j], Wm[(size_t)j * OUT_FEAT + n], acc);
        g_A2[idx] = acc;
    }
    if (idx < OUT_FEAT) {
        float acc = bm[idx];
        for (int j = 0; j < HID; ++j)
            acc = fmaf(bn[j] + be[j], Wm[(size_t)j * OUT_FEAT + idx], acc);
        g_c[idx] = acc;
    }
}

// ---------------------------------------------------------------------------
// 2) edge aggregation: one warp per edge.
//    Row gather is coalesced (64 float4 per row across 32 lanes);
//    scatter uses vector reductions red.global.add.v4.f32 (sm_90+).
// ---------------------------------------------------------------------------
__global__ __launch_bounds__(256) void edge_agg_kernel(
    const float4* __restrict__ x4,
    const float*  __restrict__ w,
    const int*    __restrict__ src,
    const int*    __restrict__ dst) {
    int warp = (blockIdx.x * blockDim.x + threadIdx.x) >> 5;
    int lane = threadIdx.x & 31;
    if (warp >= N_EDGES) return;

    int   s  = src[warp];
    int   d  = dst[warp];
    float we = w[warp];

    const float4* xs = x4   + (size_t)s * (IN_FEAT / 4);
    float4*       md = g_msg + (size_t)d * (IN_FEAT / 4);

    #pragma unroll
    for (int i = 0; i < 2; ++i) {
        int c = lane + i * 32;            // 0..63 (64 float4 per row)
        float4 v = xs[c];
        asm volatile(
            "red.global.add.v4.f32 [%0], {%1, %2, %3, %4};"
            :: "l"(md + c),
               "f"(v.x * we), "f"(v.y * we), "f"(v.z * we), "f"(v.w * we)
            : "memory");
    }
}

// ---------------------------------------------------------------------------
// 3) fused output GEMM: out[50000 x 256] = [x | msg] @ A2 + c
//    Tiles: BM=128, BN=128, BK=8; 256 threads; 8x8 register tile per thread.
// ---------------------------------------------------------------------------
__global__ __launch_bounds__(256) void gemm_out_kernel(
    const float* __restrict__ x,
    float*       __restrict__ out) {
    __shared__ float As[8][128];   // transposed A slice: As[k][m]
    __shared__ float Bs[8][128];   // B slice:            Bs[k][n]

    const float* msg = (const float*)g_msg;

    int tid  = threadIdx.x;
    int brow = blockIdx.y * 128;
    int bcol = blockIdx.x * 128;

    int tr = (tid / 16) * 8;       // this thread's m-offset (0..120)
    int tc = (tid % 16) * 8;       // this thread's n-offset (0..120)

    // Load-index mapping
    int lr  = tid >> 1;            // A: row within tile (0..127)
    int lc4 = (tid & 1) * 4;       // A: float offset within 8-wide k-slice
    int br_ = tid >> 5;            // B: k-row (0..7)
    int bc4 = (tid & 31) * 4;      // B: col offset

    float acc[8][8];
    #pragma unroll
    for (int i = 0; i < 8; ++i)
        #pragma unroll
        for (int j = 0; j < 8; ++j) acc[i][j] = 0.f;

    int arow = brow + lr;
    bool arow_ok = (arow < N_NODES);

    for (int k0 = 0; k0 < K_TOT; k0 += 8) {
        // --- stage A tile (virtual concat [x | msg]) ---
        float4 av = make_float4(0.f, 0.f, 0.f, 0.f);
        if (arow_ok) {
            const float* abase = (k0 < IN_FEAT)
                ? (x   + (size_t)arow * IN_FEAT + k0 + lc4)
                : (msg + (size_t)arow * IN_FEAT + (k0 - IN_FEAT) + lc4);
            av = *(const float4*)abase;
        }
        As[lc4 + 0][lr] = av.x;
        As[lc4 + 1][lr] = av.y;
        As[lc4 + 2][lr] = av.z;
        As[lc4 + 3][lr] = av.w;

        // --- stage B tile ---
        *(float4*)&Bs[br_][bc4] =
            *(const float4*)(g_A2 + (size_t)(k0 + br_) * OUT_FEAT + bcol + bc4);

        __syncthreads();

        #pragma unroll
        for (int kk = 0; kk < 8; ++kk) {
            float a[8], b[8];
            #pragma unroll
            for (int i = 0; i < 8; ++i) a[i] = As[kk][tr + i];
            #pragma unroll
            for (int j = 0; j < 8; ++j) b[j] = Bs[kk][tc + j];
            #pragma unroll
            for (int i = 0; i < 8; ++i)
                #pragma unroll
                for (int j = 0; j < 8; ++j)
                    acc[i][j] = fmaf(a[i], b[j], acc[i][j]);
        }
        __syncthreads();
    }

    // epilogue: add folded bias, store
    #pragma unroll
    for (int i = 0; i < 8; ++i) {
        int r = brow + tr + i;
        if (r >= N_NODES) continue;
        #pragma unroll
        for (int j = 0; j < 8; j += 4) {
            int n = bcol + tc + j;
            float4 o;
            o.x = acc[i][j + 0] + g_c[n + 0];
            o.y = acc[i][j + 1] + g_c[n + 1];
            o.z = acc[i][j + 2] + g_c[n + 2];
            o.w = acc[i][j + 3] + g_c[n + 3];
            *(float4*)(out + (size_t)r * OUT_FEAT + n) = o;
        }
    }
}

// ---------------------------------------------------------------------------
// launch
// ---------------------------------------------------------------------------
extern "C" void kernel_launch(void* const* d_in, const int* in_sizes, int n_in,
                              void* d_out, int out_size) {
    const float* x   = (const float*)d_in[0];
    const float* w   = (const float*)d_in[1];
    const int*   src = (const int*)  d_in[2];
    const int*   dst = (const int*)  d_in[3];
    const float* Wn  = (const float*)d_in[4];
    const float* bn  = (const float*)d_in[5];
    const float* We  = (const float*)d_in[6];
    const float* be  = (const float*)d_in[7];
    const float* Wm  = (const float*)d_in[8];
    const float* bm  = (const float*)d_in[9];
    float*       out = (float*)d_out;

    // 0) zero message accumulator
    zero_msg_kernel<<<1184, 256>>>();

    // 1) fold weights (independent of msg; ordered on the same stream)
    fold_weights_kernel<<<(K_TOT * OUT_FEAT + 255) / 256, 256>>>(Wn, bn, We, be, Wm, bm);

    // 2) edge aggregation: one warp per edge -> 1.6M warps
    {
        long long threads = (long long)N_EDGES * 32;
        int blocks = (int)((threads + 255) / 256);
        edge_agg_kernel<<<blocks, 256>>>((const float4*)x, w, src, dst);
    }

    // 3) fused GEMM: out = [x | msg] @ A2 + c
    {
        dim3 grid(OUT_FEAT / 128, (N_NODES + 127) / 128);
        gemm_out_kernel<<<grid, 256>>>(x, out);
    }
}

// round 5
// speedup vs baseline: 1.1426x; 1.1426x over previous
#include <cuda_runtime.h>
#include <cstdint>

#define N_NODES  50000
#define N_EDGES  1600000
#define IN_FEAT  256
#define HID      128
#define OUT_FEAT 256
#define K_FINAL  (IN_FEAT + HID)   // 384

// Device scratch (no allocations allowed)
__device__ float  g_y   [N_NODES * HID];        // x @ W_edge           (25.6 MB)
__device__ float4 g_msgh[N_NODES * (HID / 4)];  // aggregated messages  (25.6 MB)
__device__ float  g_B2  [K_FINAL * OUT_FEAT];   // [W_node@W_mlp ; W_mlp]
__device__ float  g_c   [OUT_FEAT];             // folded bias

// ---------------------------------------------------------------------------
// zero the HID-space message accumulator
// ---------------------------------------------------------------------------
__global__ void zero_msgh_kernel() {
    int total = N_NODES * (HID / 4);
    for (int i = blockIdx.x * blockDim.x + threadIdx.x; i < total;
         i += gridDim.x * blockDim.x)
        g_msgh[i] = make_float4(0.f, 0.f, 0.f, 0.f);
}

// ---------------------------------------------------------------------------
// fold weights:
//   B2[k][n]      = W_node[k,:] . W_mlp[:,n]          (k < 256)
//   B2[256+j][n]  = W_mlp[j][n]
//   c[n]          = (b_node+b_edge) . W_mlp[:,n] + b_mlp[n]
// ---------------------------------------------------------------------------
__global__ void fold_weights_kernel(const float* __restrict__ Wn,
                                    const float* __restrict__ bn,
                                    const float* __restrict__ be,
                                    const float* __restrict__ Wm,
                                    const float* __restrict__ bm) {
    int idx = blockIdx.x * blockDim.x + threadIdx.x;
    if (idx < IN_FEAT * OUT_FEAT) {
        int k = idx / OUT_FEAT, n = idx % OUT_FEAT;
        const float* wrow = Wn + (size_t)k * HID;
        float acc = 0.f;
        #pragma unroll 4
        for (int j = 0; j < HID; ++j)
            acc = fmaf(wrow[j], Wm[(size_t)j * OUT_FEAT + n], acc);
        g_B2[idx] = acc;
    } else if (idx < IN_FEAT * OUT_FEAT + HID * OUT_FEAT) {
        int r = idx - IN_FEAT * OUT_FEAT;
        g_B2[IN_FEAT * OUT_FEAT + r] = Wm[r];
    }
    if (idx < OUT_FEAT) {
        float acc = bm[idx];
        for (int j = 0; j < HID; ++j)
            acc = fmaf(bn[j] + be[j], Wm[(size_t)j * OUT_FEAT + idx], acc);
        g_c[idx] = acc;
    }
}

// ---------------------------------------------------------------------------
// edge aggregation in HID space: msgh[dst] += y[src] * w
// One warp per edge; 128 floats = exactly 32 float4 lanes.
// ---------------------------------------------------------------------------
__global__ __launch_bounds__(256) void edge_agg_hid_kernel(
    const float* __restrict__ w,
    const int*   __restrict__ src,
    const int*   __restrict__ dst) {
    int warp = (blockIdx.x * blockDim.x + threadIdx.x) >> 5;
    int lane = threadIdx.x & 31;
    if (warp >= N_EDGES) return;

    int   s  = src[warp];
    int   d  = dst[warp];
    float we = w[warp];

    const float4* ys = (const float4*)g_y + (size_t)s * (HID / 4);
    float4*       md = g_msgh + (size_t)d * (HID / 4);

    float4 v = ys[lane];
    asm volatile(
        "red.global.add.v4.f32 [%0], {%1, %2, %3, %4};"
        :: "l"(md + lane),
           "f"(v.x * we), "f"(v.y * we), "f"(v.z * we), "f"(v.w * we)
        : "memory");
}

// ---------------------------------------------------------------------------
// split-precision tf32 GEMM (3-term: Ahi*Bhi + Alo*Bhi + Ahi*Blo ~ fp32)
// C[M x NOUT] = [A0 | A1] @ B (+ bias)
// BM=128, BN=128, BK=32; 256 threads; 8 warps 4(m) x 2(n); warp tile 32x64.
// A smem stride 36, B stride 136 -> conflict-free fragment loads.
// Dynamic smem: (128*36 + 32*136) * 2 arrays * 4B = 71680 B.
// ---------------------------------------------------------------------------
__device__ __forceinline__ void split_tf32(float f, uint32_t& hi, uint32_t& lo) {
    uint32_t h;
    asm("cvt.rna.tf32.f32 %0, %1;" : "=r"(h) : "f"(f));
    float r = f - __uint_as_float(h);   // exact
    uint32_t l;
    asm("cvt.rna.tf32.f32 %0, %1;" : "=r"(l) : "f"(r));
    hi = h; lo = l;
}

#define MMA_TF32(C, A, B0, B1)                                              \
    asm volatile(                                                           \
        "mma.sync.aligned.m16n8k8.row.col.f32.tf32.tf32.f32 "               \
        "{%0,%1,%2,%3}, {%4,%5,%6,%7}, {%8,%9}, {%0,%1,%2,%3};"             \
        : "+f"((C)[0]), "+f"((C)[1]), "+f"((C)[2]), "+f"((C)[3])            \
        : "r"((A)[0]), "r"((A)[1]), "r"((A)[2]), "r"((A)[3]),               \
          "r"(B0), "r"(B1))

#define AS_ELEMS (128 * 36)
#define BS_ELEMS (32 * 136)
#define GEMM_SMEM_BYTES ((AS_ELEMS + BS_ELEMS) * 2 * 4)

template<int KTOT, int NOUT, bool CONCAT, bool BIAS>
__global__ __launch_bounds__(256) void gemm_tf32_kernel(
    const float* __restrict__ A0,    // [M x IN_FEAT]
    const float* __restrict__ A1,    // [M x HID]  (used if CONCAT)
    const float* __restrict__ B,     // [KTOT x NOUT] row-major
    const float* __restrict__ bias,  // [NOUT]     (used if BIAS)
    float*       __restrict__ C,
    int M) {
    extern __shared__ uint32_t smem[];
    uint32_t* Ash = smem;
    uint32_t* Asl = Ash + AS_ELEMS;
    uint32_t* Bsh = Asl + AS_ELEMS;
    uint32_t* Bsl = Bsh + BS_ELEMS;

    const int tid  = threadIdx.x;
    const int brow = blockIdx.y * 128;
    const int bcol = blockIdx.x * 128;

    const int warp = tid >> 5, lane = tid & 31;
    const int g = lane >> 2, tg = lane & 3;
    const int wm = warp >> 1, wn = warp & 1;

    float acc[2][8][4];
    #pragma unroll
    for (int mt = 0; mt < 2; ++mt)
        #pragma unroll
        for (int nt = 0; nt < 8; ++nt)
            #pragma unroll
            for (int i = 0; i < 4; ++i) acc[mt][nt][i] = 0.f;

    // staging indices
    const int a_m  = tid >> 3;          // 0..31
    const int a_k  = (tid & 7) * 4;     // 0..28
    const int b_k0 = tid >> 5;          // 0..7
    const int b_n  = (tid & 31) * 4;    // 0..124

    for (int k0 = 0; k0 < KTOT; k0 += 32) {
        // ---- stage A ----
        #pragma unroll
        for (int i = 0; i < 4; ++i) {
            int m = a_m + i * 32;
            int r = brow + m;
            float4 v = make_float4(0.f, 0.f, 0.f, 0.f);
            if (r < M) {
                int kg = k0 + a_k;
                const float* p = (!CONCAT || kg < IN_FEAT)
                    ? (A0 + (size_t)r * IN_FEAT + kg)
                    : (A1 + (size_t)r * HID + (kg - IN_FEAT));
                v = *(const float4*)p;
            }
            int o = m * 36 + a_k;
            split_tf32(v.x, Ash[o + 0], Asl[o + 0]);
            split_tf32(v.y, Ash[o + 1], Asl[o + 1]);
            split_tf32(v.z, Ash[o + 2], Asl[o + 2]);
            split_tf32(v.w, Ash[o + 3], Asl[o + 3]);
        }
        // ---- stage B ----
        #pragma unroll
        for (int i = 0; i < 4; ++i) {
            int k = b_k0 + i * 8;
            float4 v = *(const float4*)(B + (size_t)(k0 + k) * NOUT + bcol + b_n);
            int o = k * 136 + b_n;
            split_tf32(v.x, Bsh[o + 0], Bsl[o + 0]);
            split_tf32(v.y, Bsh[o + 1], Bsl[o + 1]);
            split_tf32(v.z, Bsh[o + 2], Bsl[o + 2]);
            split_tf32(v.w, Bsh[o + 3], Bsl[o + 3]);
        }
        __syncthreads();

        #pragma unroll
        for (int ks8 = 0; ks8 < 4; ++ks8) {
            const int ks = ks8 * 8;
            uint32_t afh[2][4], afl[2][4];
            #pragma unroll
            for (int mt = 0; mt < 2; ++mt) {
                int m0 = wm * 32 + mt * 16 + g;
                int o00 = m0 * 36 + ks + tg;
                int o10 = (m0 + 8) * 36 + ks + tg;
                afh[mt][0] = Ash[o00];     afl[mt][0] = Asl[o00];
                afh[mt][1] = Ash[o10];     afl[mt][1] = Asl[o10];
                afh[mt][2] = Ash[o00 + 4]; afl[mt][2] = Asl[o00 + 4];
                afh[mt][3] = Ash[o10 + 4]; afl[mt][3] = Asl[o10 + 4];
            }
            #pragma unroll
            for (int nt = 0; nt < 8; ++nt) {
                int n = wn * 64 + nt * 8 + g;
                int ob0 = (ks + tg) * 136 + n;
                int ob1 = (ks + tg + 4) * 136 + n;
                uint32_t bh0 = Bsh[ob0], bh1 = Bsh[ob1];
                uint32_t bl0 = Bsl[ob0], bl1 = Bsl[ob1];
                #pragma unroll
                for (int mt = 0; mt < 2; ++mt) {
                    MMA_TF32(acc[mt][nt], afh[mt], bh0, bh1);
                    MMA_TF32(acc[mt][nt], afl[mt], bh0, bh1);
                    MMA_TF32(acc[mt][nt], afh[mt], bl0, bl1);
                }
            }
        }
        __syncthreads();
    }

    // ---- epilogue ----
    #pragma unroll
    for (int mt = 0; mt < 2; ++mt) {
        int row0 = brow + wm * 32 + mt * 16 + g;
        int row1 = row0 + 8;
        #pragma unroll
        for (int nt = 0; nt < 8; ++nt) {
            int col = bcol + wn * 64 + nt * 8 + tg * 2;
            float b0 = BIAS ? bias[col]     : 0.f;
            float b1 = BIAS ? bias[col + 1] : 0.f;
            if (row0 < M) {
                float2 o = make_float2(acc[mt][nt][0] + b0, acc[mt][nt][1] + b1);
                *(float2*)(C + (size_t)row0 * NOUT + col) = o;
            }
            if (row1 < M) {
                float2 o = make_float2(acc[mt][nt][2] + b0, acc[mt][nt][3] + b1);
                *(float2*)(C + (size_t)row1 * NOUT + col) = o;
            }
        }
    }
}

// ---------------------------------------------------------------------------
// launch
// ---------------------------------------------------------------------------
extern "C" void kernel_launch(void* const* d_in, const int* in_sizes, int n_in,
                              void* d_out, int out_size) {
    const float* x   = (const float*)d_in[0];
    const float* w   = (const float*)d_in[1];
    const int*   src = (const int*)  d_in[2];
    const int*   dst = (const int*)  d_in[3];
    const float* Wn  = (const float*)d_in[4];
    const float* bn  = (const float*)d_in[5];
    const float* We  = (const float*)d_in[6];
    const float* be  = (const float*)d_in[7];
    const float* Wm  = (const float*)d_in[8];
    const float* bm  = (const float*)d_in[9];
    float*       out = (float*)d_out;

    // Device addresses of __device__ symbols (host-side &symbol is INVALID)
    float* y    = nullptr;  cudaGetSymbolAddress((void**)&y,    g_y);
    float* msgh = nullptr;  cudaGetSymbolAddress((void**)&msgh, g_msgh);
    float* B2   = nullptr;  cudaGetSymbolAddress((void**)&B2,   g_B2);
    float* cvec = nullptr;  cudaGetSymbolAddress((void**)&cvec, g_c);

    // allow >48KB dynamic smem for both GEMM instantiations
    cudaFuncSetAttribute(gemm_tf32_kernel<IN_FEAT, HID, false, false>,
                         cudaFuncAttributeMaxDynamicSharedMemorySize,
                         GEMM_SMEM_BYTES);
    cudaFuncSetAttribute(gemm_tf32_kernel<K_FINAL, OUT_FEAT, true, true>,
                         cudaFuncAttributeMaxDynamicSharedMemorySize,
                         GEMM_SMEM_BYTES);

    // 0) zero message accumulator
    zero_msgh_kernel<<<640, 256>>>();

    // 1) fold weights
    {
        int total = IN_FEAT * OUT_FEAT + HID * OUT_FEAT;   // 98304
        fold_weights_kernel<<<(total + 255) / 256, 256>>>(Wn, bn, be, Wm, bm);
    }

    // 2) y = x @ W_edge   [50000 x 128]
    {
        dim3 grid(1, (N_NODES + 127) / 128);
        gemm_tf32_kernel<IN_FEAT, HID, false, false>
            <<<grid, 256, GEMM_SMEM_BYTES>>>(x, nullptr, We, nullptr, y, N_NODES);
    }

    // 3) edge aggregation in HID space
    {
        long long threads = (long long)N_EDGES * 32;
        int blocks = (int)((threads + 255) / 256);
        edge_agg_hid_kernel<<<blocks, 256>>>(w, src, dst);
    }

    // 4) out = [x | msgh] @ B2 + c   [50000 x 256]
    {
        dim3 grid(OUT_FEAT / 128, (N_NODES + 127) / 128);
        gemm_tf32_kernel<K_FINAL, OUT_FEAT, true, true>
            <<<grid, 256, GEMM_SMEM_BYTES>>>(x, msgh, B2, cvec, out, N_NODES);
    }
}

// round 8
// speedup vs baseline: 1.3114x; 1.1478x over previous
#include <cuda_runtime.h>
#include <cuda_fp16.h>
#include <cstdint>

#define N_NODES  50000
#define N_EDGES  1600000
#define IN_FEAT  256
#define HID      128
#define OUT_FEAT 256
#define K_FINAL  (IN_FEAT + HID)   // 384

// ---------------------------------------------------------------------------
// Device scratch
// ---------------------------------------------------------------------------
__device__ float  g_y   [N_NODES * HID];        // x @ W_edge  (25.6 MB)
__device__ float4 g_msgh[N_NODES * (HID / 4)];  // messages    (25.6 MB)
__device__ __half g_Bth [OUT_FEAT * K_FINAL];   // B2^T hi  [N=256][K=384]
__device__ __half g_Btl [OUT_FEAT * K_FINAL];   // B2^T lo
__device__ __half g_Weth[HID * IN_FEAT];        // We^T hi  [N=128][K=256]
__device__ __half g_Wetl[HID * IN_FEAT];        // We^T lo
__device__ float  g_c   [OUT_FEAT];             // folded bias

// ---------------------------------------------------------------------------
// zero the HID-space message accumulator
// ---------------------------------------------------------------------------
__global__ void zero_msgh_kernel() {
    int total = N_NODES * (HID / 4);
    for (int i = blockIdx.x * blockDim.x + threadIdx.x; i < total;
         i += gridDim.x * blockDim.x)
        g_msgh[i] = make_float4(0.f, 0.f, 0.f, 0.f);
}

// ---------------------------------------------------------------------------
// fp16 split helpers
// ---------------------------------------------------------------------------
__device__ __forceinline__ void split_h(float v, __half& hi, __half& lo) {
    hi = __float2half_rn(v);
    lo = __float2half_rn(v - __half2float(hi));
}
__device__ __forceinline__ uint32_t packh(__half a, __half b) {
    __half2 h2 = __halves2half2(a, b);
    return *(uint32_t*)&h2;
}

// ---------------------------------------------------------------------------
// fold weights to transposed, fp16-split form:
//   B2t[n][k] = (k<256 ? W_node[k,:] . W_mlp[:,n] : W_mlp[k-256][n])
//   c[n]      = (b_node+b_edge) . W_mlp[:,n] + b_mlp[n]
// One block per output column n; thread k covers the K dimension.
// ---------------------------------------------------------------------------
__global__ void fold_b2t_kernel(const float* __restrict__ Wn,
                                const float* __restrict__ bn,
                                const float* __restrict__ be,
                                const float* __restrict__ Wm,
                                const float* __restrict__ bm) {
    __shared__ float sWm[HID];
    int n = blockIdx.x;
    int k = threadIdx.x;                 // 0..383
    if (k < HID) sWm[k] = Wm[(size_t)k * OUT_FEAT + n];
    __syncthreads();

    float val;
    if (k < IN_FEAT) {
        const float* wr = Wn + (size_t)k * HID;
        float acc = 0.f;
        #pragma unroll 4
        for (int j = 0; j < HID; ++j) acc = fmaf(wr[j], sWm[j], acc);
        val = acc;
    } else {
        val = sWm[k - IN_FEAT];
    }
    __half h, l;
    split_h(val, h, l);
    g_Bth[(size_t)n * K_FINAL + k] = h;
    g_Btl[(size_t)n * K_FINAL + k] = l;

    if (k == 0) {
        float acc = bm[n];
        for (int j = 0; j < HID; ++j) acc = fmaf(bn[j] + be[j], sWm[j], acc);
        g_c[n] = acc;
    }
}

// We^T split: Wet[h][k] = We[k][h]
__global__ void fold_wet_kernel(const float* __restrict__ We) {
    int idx = blockIdx.x * blockDim.x + threadIdx.x;
    if (idx >= IN_FEAT * HID) return;
    int k = idx >> 7;          // /HID
    int h = idx & (HID - 1);
    float v = We[idx];
    __half hh, hl;
    split_h(v, hh, hl);
    g_Weth[(size_t)h * IN_FEAT + k] = hh;
    g_Wetl[(size_t)h * IN_FEAT + k] = hl;
}

// ---------------------------------------------------------------------------
// edge aggregation (REDG-floor bound)
// ---------------------------------------------------------------------------
__global__ __launch_bounds__(256) void edge_agg_hid_kernel(
    const float* __restrict__ w,
    const int*   __restrict__ src,
    const int*   __restrict__ dst) {
    int warp = (blockIdx.x * blockDim.x + threadIdx.x) >> 5;
    int lane = threadIdx.x & 31;
    if (warp >= N_EDGES) return;

    int   s  = src[warp];
    int   d  = dst[warp];
    float we = w[warp];

    const float4* ys = (const float4*)g_y + (size_t)s * (HID / 4);
    float4*       md = g_msgh + (size_t)d * (HID / 4);

    float4 v = ys[lane];
    asm volatile(
        "red.global.add.v4.f32 [%0], {%1, %2, %3, %4};"
        :: "l"(md + lane),
           "f"(v.x * we), "f"(v.y * we), "f"(v.z * we), "f"(v.w * we)
        : "memory");
}

// ---------------------------------------------------------------------------
// split-precision fp16 GEMM (3-term: Ah*Bh + Al*Bh + Ah*Bl ~ fp32)
// C[M x NOUT] = [A0 | A1] @ Bt^T (+ bias), Bt pre-split fp16 [NOUT][KTOT]
// BM=128, BN=128, BK=32; 256 threads; 8 warps 4(m) x 2(n); warp tile 32x64;
// mma.sync.m16n8k16.f16, fp32 accumulators.
// Smem: uint32 (fp16-pair) arrays, row stride 20 -> conflict-free frag loads
//   ((g*20 + tg) mod 32 covers all 32 banks).  Total 4*128*20*4 = 40960 B.
// ---------------------------------------------------------------------------
#define MMA_F16(C, A, B0, B1)                                               \
    asm volatile(                                                           \
        "mma.sync.aligned.m16n8k16.row.col.f32.f16.f16.f32 "                \
        "{%0,%1,%2,%3}, {%4,%5,%6,%7}, {%8,%9}, {%0,%1,%2,%3};"             \
        : "+f"((C)[0]), "+f"((C)[1]), "+f"((C)[2]), "+f"((C)[3])            \
        : "r"((A)[0]), "r"((A)[1]), "r"((A)[2]), "r"((A)[3]),               \
          "r"(B0), "r"(B1))

template<int KTOT, int NOUT, bool CONCAT, bool BIAS>
__global__ __launch_bounds__(256) void gemm_f16_kernel(
    const float*  __restrict__ A0,    // [M x IN_FEAT]
    const float*  __restrict__ A1,    // [M x HID]   (used if CONCAT)
    const __half* __restrict__ Bh,    // [NOUT x KTOT] K-major, hi
    const __half* __restrict__ Bl,    // [NOUT x KTOT] K-major, lo
    const float*  __restrict__ bias,  // [NOUT]      (used if BIAS)
    float*        __restrict__ C,
    int M) {
    __shared__ uint32_t Ash[128 * 20];   // [m][kp] fp16 pairs, 16 used + 4 pad
    __shared__ uint32_t Asl[128 * 20];
    __shared__ uint32_t Bsh[128 * 20];   // [n][kp]
    __shared__ uint32_t Bsl[128 * 20];

    const int tid  = threadIdx.x;
    const int brow = blockIdx.y * 128;
    const int bcol = blockIdx.x * 128;

    const int warp = tid >> 5, lane = tid & 31;
    const int g = lane >> 2, tg = lane & 3;
    const int wm = warp >> 1, wn = warp & 1;

    float acc[2][8][4];
    #pragma unroll
    for (int mt = 0; mt < 2; ++mt)
        #pragma unroll
        for (int nt = 0; nt < 8; ++nt)
            #pragma unroll
            for (int i = 0; i < 4; ++i) acc[mt][nt][i] = 0.f;

    // staging indices
    const int a_m  = tid >> 3;            // 0..31
    const int a_k  = (tid & 7) * 4;       // float offset 0..28
    const int a_kp = (tid & 7) * 2;       // pair offset 0..14
    const int b_n  = tid >> 1;            // 0..127
    const int b_kp = (tid & 1) * 8;       // pair offset 0 or 8

    for (int k0 = 0; k0 < KTOT; k0 += 32) {
        // ---- stage A: fp32 -> (hi, lo) fp16 pairs ----
        #pragma unroll
        for (int i = 0; i < 4; ++i) {
            int m = a_m + i * 32;
            int r = brow + m;
            float4 v = make_float4(0.f, 0.f, 0.f, 0.f);
            if (r < M) {
                int kg = k0 + a_k;
                const float* p = (!CONCAT || kg < IN_FEAT)
                    ? (A0 + (size_t)r * IN_FEAT + kg)
                    : (A1 + (size_t)r * HID + (kg - IN_FEAT));
                v = *(const float4*)p;
            }
            __half hx, lx, hy, ly, hz, lz, hw, lw;
            split_h(v.x, hx, lx); split_h(v.y, hy, ly);
            split_h(v.z, hz, lz); split_h(v.w, hw, lw);
            int o = m * 20 + a_kp;
            Ash[o]     = packh(hx, hy);
            Ash[o + 1] = packh(hz, hw);
            Asl[o]     = packh(lx, ly);
            Asl[o + 1] = packh(lz, lw);
        }
        // ---- stage B: pre-split fp16, straight copy ----
        {
            int n = bcol + b_n;
            const uint4* ph = (const uint4*)((const uint32_t*)(Bh + (size_t)n * KTOT + k0) + b_kp);
            const uint4* pl = (const uint4*)((const uint32_t*)(Bl + (size_t)n * KTOT + k0) + b_kp);
            uint4 vh0 = ph[0], vh1 = ph[1];
            uint4 vl0 = pl[0], vl1 = pl[1];
            int o = b_n * 20 + b_kp;
            Bsh[o + 0] = vh0.x; Bsh[o + 1] = vh0.y; Bsh[o + 2] = vh0.z; Bsh[o + 3] = vh0.w;
            Bsh[o + 4] = vh1.x; Bsh[o + 5] = vh1.y; Bsh[o + 6] = vh1.z; Bsh[o + 7] = vh1.w;
            Bsl[o + 0] = vl0.x; Bsl[o + 1] = vl0.y; Bsl[o + 2] = vl0.z; Bsl[o + 3] = vl0.w;
            Bsl[o + 4] = vl1.x; Bsl[o + 5] = vl1.y; Bsl[o + 6] = vl1.z; Bsl[o + 7] = vl1.w;
        }
        __syncthreads();

        #pragma unroll
        for (int ks2 = 0; ks2 < 2; ++ks2) {     // two K=16 steps per 32-k tile
            const int kb = ks2 * 8;             // pair offset
            uint32_t afh[2][4], afl[2][4];
            #pragma unroll
            for (int mt = 0; mt < 2; ++mt) {
                int m0 = wm * 32 + mt * 16 + g;
                int o00 = m0 * 20 + kb + tg;
                int o10 = (m0 + 8) * 20 + kb + tg;
                afh[mt][0] = Ash[o00];     afl[mt][0] = Asl[o00];
                afh[mt][1] = Ash[o10];     afl[mt][1] = Asl[o10];
                afh[mt][2] = Ash[o00 + 4]; afl[mt][2] = Asl[o00 + 4];
                afh[mt][3] = Ash[o10 + 4]; afl[mt][3] = Asl[o10 + 4];
            }
            #pragma unroll
            for (int nt = 0; nt < 8; ++nt) {
                int n = wn * 64 + nt * 8 + g;
                int ob = n * 20 + kb + tg;
                uint32_t bh0 = Bsh[ob], bh1 = Bsh[ob + 4];
                uint32_t bl0 = Bsl[ob], bl1 = Bsl[ob + 4];
                #pragma unroll
                for (int mt = 0; mt < 2; ++mt) {
                    MMA_F16(acc[mt][nt], afh[mt], bh0, bh1);
                    MMA_F16(acc[mt][nt], afl[mt], bh0, bh1);
                    MMA_F16(acc[mt][nt], afh[mt], bl0, bl1);
                }
            }
        }
        __syncthreads();
    }

    // ---- epilogue ----
    #pragma unroll
    for (int mt = 0; mt < 2; ++mt) {
        int row0 = brow + wm * 32 + mt * 16 + g;
        int row1 = row0 + 8;
        #pragma unroll
        for (int nt = 0; nt < 8; ++nt) {
            int col = bcol + wn * 64 + nt * 8 + tg * 2;
            float b0 = BIAS ? bias[col]     : 0.f;
            float b1 = BIAS ? bias[col + 1] : 0.f;
            if (row0 < M) {
                float2 o = make_float2(acc[mt][nt][0] + b0, acc[mt][nt][1] + b1);
                *(float2*)(C + (size_t)row0 * NOUT + col) = o;
            }
            if (row1 < M) {
                float2 o = make_float2(acc[mt][nt][2] + b0, acc[mt][nt][3] + b1);
                *(float2*)(C + (size_t)row1 * NOUT + col) = o;
            }
        }
    }
}

// ---------------------------------------------------------------------------
// launch
// ---------------------------------------------------------------------------
extern "C" void kernel_launch(void* const* d_in, const int* in_sizes, int n_in,
                              void* d_out, int out_size) {
    const float* x   = (const float*)d_in[0];
    const float* w   = (const float*)d_in[1];
    const int*   src = (const int*)  d_in[2];
    const int*   dst = (const int*)  d_in[3];
    const float* Wn  = (const float*)d_in[4];
    const float* bn  = (const float*)d_in[5];
    const float* We  = (const float*)d_in[6];
    const float* be  = (const float*)d_in[7];
    const float* Wm  = (const float*)d_in[8];
    const float* bm  = (const float*)d_in[9];
    float*       out = (float*)d_out;

    // device addresses of __device__ symbols
    float *y, *msgh, *cvec;
    __half *Bth, *Btl, *Weth, *Wetl;
    cudaGetSymbolAddress((void**)&y,    g_y);
    cudaGetSymbolAddress((void**)&msgh, g_msgh);
    cudaGetSymbolAddress((void**)&cvec, g_c);
    cudaGetSymbolAddress((void**)&Bth,  g_Bth);
    cudaGetSymbolAddress((void**)&Btl,  g_Btl);
    cudaGetSymbolAddress((void**)&Weth, g_Weth);
    cudaGetSymbolAddress((void**)&Wetl, g_Wetl);

    // 0) zero message accumulator
    zero_msgh_kernel<<<640, 256>>>();

    // 1) fold weights (transposed + fp16-split)
    fold_b2t_kernel<<<OUT_FEAT, K_FINAL>>>(Wn, bn, be, Wm, bm);
    fold_wet_kernel<<<(IN_FEAT * HID + 255) / 256, 256>>>(We);

    // 2) y = x @ W_edge   [50000 x 128]
    {
        dim3 grid(1, (N_NODES + 127) / 128);
        gemm_f16_kernel<IN_FEAT, HID, false, false>
            <<<grid, 256>>>(x, nullptr, Weth, Wetl, nullptr, y, N_NODES);
    }

    // 3) edge aggregation in HID space
    {
        long long threads = (long long)N_EDGES * 32;
        int blocks = (int)((threads + 255) / 256);
        edge_agg_hid_kernel<<<blocks, 256>>>(w, src, dst);
    }

    // 4) out = [x | msgh] @ B2 + c   [50000 x 256]
    {
        dim3 grid(OUT_FEAT / 128, (N_NODES + 127) / 128);
        gemm_f16_kernel<K_FINAL, OUT_FEAT, true, true>
            <<<grid, 256>>>(x, msgh, Bth, Btl, cvec, out, N_NODES);
    }
}

// round 9
// speedup vs baseline: 1.8706x; 1.4264x over previous
#include <cuda_runtime.h>
#include <cuda_fp16.h>
#include <cstdint>

#define N_NODES  50000
#define N_EDGES  1600000
#define IN_FEAT  256
#define HID      128
#define OUT_FEAT 256
#define K_FINAL  (IN_FEAT + HID)   // 384

// ---------------------------------------------------------------------------
// Device scratch
// ---------------------------------------------------------------------------
__device__ float  g_y   [N_NODES * HID];         // x @ W_edge, fp32 (25.6 MB)
__device__ __half g_xh  [N_NODES * IN_FEAT];     // x split hi   (25.6 MB)
__device__ __half g_xl  [N_NODES * IN_FEAT];     // x split lo
__device__ __half g_mh  [N_NODES * HID];         // msg split hi (12.8 MB)
__device__ __half g_ml  [N_NODES * HID];         // msg split lo
__device__ __half g_Bth [OUT_FEAT * K_FINAL];    // B2^T hi [256][384]
__device__ __half g_Btl [OUT_FEAT * K_FINAL];    // B2^T lo
__device__ __half g_Weth[HID * IN_FEAT];         // We^T hi [128][256]
__device__ __half g_Wetl[HID * IN_FEAT];         // We^T lo
__device__ float  g_c   [OUT_FEAT];              // folded bias
// CSR-by-dst
__device__ int    g_cnt [N_NODES];               // histogram, then cursor
__device__ int    g_off [N_NODES + 1];
__device__ int    g_srcs[N_EDGES];
__device__ float  g_ws  [N_EDGES];

// ---------------------------------------------------------------------------
// helpers
// ---------------------------------------------------------------------------
__device__ __forceinline__ void split_h(float v, __half& hi, __half& lo) {
    hi = __float2half_rn(v);
    lo = __float2half_rn(v - __half2float(hi));
}
__device__ __forceinline__ uint32_t packh(__half a, __half b) {
    __half2 h2 = __halves2half2(a, b);
    return *(uint32_t*)&h2;
}
__device__ __forceinline__ uint32_t smem_u32(const void* p) {
    uint32_t a;
    asm("{ .reg .u64 t; cvta.to.shared.u64 t, %1; cvt.u32.u64 %0, t; }"
        : "=r"(a) : "l"(p));
    return a;
}
#define CP_ASYNC16(dst, src, sz) \
    asm volatile("cp.async.cg.shared.global [%0], [%1], 16, %2;" \
                 :: "r"(dst), "l"(src), "r"(sz) : "memory")
#define CP_COMMIT()  asm volatile("cp.async.commit_group;" ::: "memory")
#define CP_WAIT1()   asm volatile("cp.async.wait_group 1;"  ::: "memory")

// ---------------------------------------------------------------------------
// CSR build: zero -> hist -> scan -> scatter
// ---------------------------------------------------------------------------
__global__ void zero_cnt_kernel() {
    int i = blockIdx.x * blockDim.x + threadIdx.x;
    if (i < N_NODES) g_cnt[i] = 0;
}

__global__ void hist_kernel(const int* __restrict__ dst) {
    int e = blockIdx.x * blockDim.x + threadIdx.x;
    if (e < N_EDGES) atomicAdd(&g_cnt[dst[e]], 1);
}

__global__ __launch_bounds__(1024) void scan_kernel() {
    __shared__ int part[1024];
    const int tid = threadIdx.x;
    const int C = (N_NODES + 1023) / 1024;          // 49
    const int base = tid * C;
    int s = 0;
    for (int j = 0; j < C; ++j) {
        int i = base + j;
        if (i < N_NODES) s += g_cnt[i];
    }
    part[tid] = s;
    __syncthreads();
    for (int d = 1; d < 1024; d <<= 1) {            // Hillis-Steele inclusive
        int v = 0;
        if (tid >= d) v = part[tid - d];
        __syncthreads();
        if (tid >= d) part[tid] += v;
        __syncthreads();
    }
    int run = (tid == 0) ? 0 : part[tid - 1];
    for (int j = 0; j < C; ++j) {
        int i = base + j;
        if (i < N_NODES) {
            int c = g_cnt[i];
            g_off[i] = run;
            g_cnt[i] = run;                          // cursor for scatter
            run += c;
        }
    }
    if (tid == 0) g_off[N_NODES] = part[1023];
}

__global__ void scatter_kernel(const int* __restrict__ src,
                               const int* __restrict__ dst,
                               const float* __restrict__ w) {
    int e = blockIdx.x * blockDim.x + threadIdx.x;
    if (e >= N_EDGES) return;
    int d = dst[e];
    int p = atomicAdd(&g_cnt[d], 1);
    g_srcs[p] = src[e];
    g_ws[p]   = w[e];
}

// ---------------------------------------------------------------------------
// pre-split x into fp16 hi/lo
// ---------------------------------------------------------------------------
__global__ void split_x_kernel(const float4* __restrict__ x4) {
    int i = blockIdx.x * blockDim.x + threadIdx.x;
    if (i >= N_NODES * IN_FEAT / 4) return;
    float4 v = x4[i];
    __half h0, l0, h1, l1, h2, l2, h3, l3;
    split_h(v.x, h0, l0); split_h(v.y, h1, l1);
    split_h(v.z, h2, l2); split_h(v.w, h3, l3);
    uint2 H = make_uint2(packh(h0, h1), packh(h2, h3));
    uint2 L = make_uint2(packh(l0, l1), packh(l2, l3));
    *(uint2*)&g_xh[i * 4] = H;
    *(uint2*)&g_xl[i * 4] = L;
}

// ---------------------------------------------------------------------------
// fold weights (transposed + fp16-split)
// ---------------------------------------------------------------------------
__global__ void fold_b2t_kernel(const float* __restrict__ Wn,
                                const float* __restrict__ bn,
                                const float* __restrict__ be,
                                const float* __restrict__ Wm,
                                const float* __restrict__ bm) {
    __shared__ float sWm[HID];
    int n = blockIdx.x;
    int k = threadIdx.x;                 // 0..383
    if (k < HID) sWm[k] = Wm[(size_t)k * OUT_FEAT + n];
    __syncthreads();

    float val;
    if (k < IN_FEAT) {
        const float* wr = Wn + (size_t)k * HID;
        float acc = 0.f;
        #pragma unroll 4
        for (int j = 0; j < HID; ++j) acc = fmaf(wr[j], sWm[j], acc);
        val = acc;
    } else {
        val = sWm[k - IN_FEAT];
    }
    __half h, l;
    split_h(val, h, l);
    g_Bth[(size_t)n * K_FINAL + k] = h;
    g_Btl[(size_t)n * K_FINAL + k] = l;

    if (k == 0) {
        float acc = bm[n];
        for (int j = 0; j < HID; ++j) acc = fmaf(bn[j] + be[j], sWm[j], acc);
        g_c[n] = acc;
    }
}

__global__ void fold_wet_kernel(const float* __restrict__ We) {
    int idx = blockIdx.x * blockDim.x + threadIdx.x;
    if (idx >= IN_FEAT * HID) return;
    int k = idx >> 7;
    int h = idx & (HID - 1);
    float v = We[idx];
    __half hh, hl;
    split_h(v, hh, hl);
    g_Weth[(size_t)h * IN_FEAT + k] = hh;
    g_Wetl[(size_t)h * IN_FEAT + k] = hl;
}

// ---------------------------------------------------------------------------
// CSR aggregation: one warp per node, register accumulation, no atomics.
// msg[v] = sum_{e in seg(v)} y[src_e] * w_e ; output split fp16 hi/lo.
// ---------------------------------------------------------------------------
__global__ __launch_bounds__(256) void agg_csr_kernel() {
    int v    = (blockIdx.x * blockDim.x + threadIdx.x) >> 5;
    int lane = threadIdx.x & 31;
    if (v >= N_NODES) return;

    int b  = g_off[v];
    int e2 = g_off[v + 1];
    const float4* yb = (const float4*)g_y;

    float4 acc = make_float4(0.f, 0.f, 0.f, 0.f);
    int i = b;
    for (; i + 2 <= e2; i += 2) {
        int   s0 = g_srcs[i],     s1 = g_srcs[i + 1];
        float w0 = g_ws[i],       w1 = g_ws[i + 1];
        float4 t0 = yb[(size_t)s0 * 32 + lane];
        float4 t1 = yb[(size_t)s1 * 32 + lane];
        acc.x += t0.x * w0 + t1.x * w1;
        acc.y += t0.y * w0 + t1.y * w1;
        acc.z += t0.z * w0 + t1.z * w1;
        acc.w += t0.w * w0 + t1.w * w1;
    }
    if (i < e2) {
        int   s0 = g_srcs[i];
        float w0 = g_ws[i];
        float4 t0 = yb[(size_t)s0 * 32 + lane];
        acc.x += t0.x * w0; acc.y += t0.y * w0;
        acc.z += t0.z * w0; acc.w += t0.w * w0;
    }

    __half h0, l0, h1, l1, h2, l2, h3, l3;
    split_h(acc.x, h0, l0); split_h(acc.y, h1, l1);
    split_h(acc.z, h2, l2); split_h(acc.w, h3, l3);
    uint2 H = make_uint2(packh(h0, h1), packh(h2, h3));
    uint2 L = make_uint2(packh(l0, l1), packh(l2, l3));
    *(uint2*)&g_mh[(size_t)v * HID + lane * 4] = H;
    *(uint2*)&g_ml[(size_t)v * HID + lane * 4] = L;
}

// ---------------------------------------------------------------------------
// split-precision fp16 GEMM, cp.async double-buffered.
// C[M x NOUT] = [A0 | A1] @ Bt^T (+ bias); all operands pre-split fp16.
// BM=128, BN=128, BK=32; 256 threads; warp tile 32x64; mma.m16n8k16.
// Smem stage: 4 arrays of 128x20 uint32 (16 data words + 4 pad per row)
//   = 40960 B; 2 stages = 81920 B dynamic.
// ---------------------------------------------------------------------------
#define MMA_F16(C, A, B0, B1)                                               \
    asm volatile(                                                           \
        "mma.sync.aligned.m16n8k16.row.col.f32.f16.f16.f32 "                \
        "{%0,%1,%2,%3}, {%4,%5,%6,%7}, {%8,%9}, {%0,%1,%2,%3};"             \
        : "+f"((C)[0]), "+f"((C)[1]), "+f"((C)[2]), "+f"((C)[3])            \
        : "r"((A)[0]), "r"((A)[1]), "r"((A)[2]), "r"((A)[3]),               \
          "r"(B0), "r"(B1))

#define STAGE_BYTES 40960
#define GEMM_SMEM   (2 * STAGE_BYTES)

template<int KTOT, int NOUT, bool CONCAT, bool BIAS>
__global__ __launch_bounds__(256) void gemm_f16_kernel(
    const __half* __restrict__ A0h, const __half* __restrict__ A0l,  // [M x IN_FEAT]
    const __half* __restrict__ A1h, const __half* __restrict__ A1l,  // [M x HID]
    const __half* __restrict__ Bh,  const __half* __restrict__ Bl,   // [NOUT x KTOT]
    const float*  __restrict__ bias,
    float*        __restrict__ C,
    int M) {
    extern __shared__ uint32_t sm[];
    const uint32_t smb = smem_u32(sm);

    const int tid  = threadIdx.x;
    const int brow = blockIdx.y * 128;
    const int bcol = blockIdx.x * 128;

    const int warp = tid >> 5, lane = tid & 31;
    const int g = lane >> 2, tg = lane & 3;
    const int wm = warp >> 1, wn = warp & 1;

    constexpr int T = KTOT / 32;

    float acc[2][8][4];
    #pragma unroll
    for (int mt = 0; mt < 2; ++mt)
        #pragma unroll
        for (int nt = 0; nt < 8; ++nt)
            #pragma unroll
            for (int i = 0; i < 4; ++i) acc[mt][nt][i] = 0.f;

    // stage issuer: 16B cp.async chunks. chunk id = row*4 + c (c in 0..3);
    // row has 16 data words at stride 20; chunk c covers words c*4..c*4+3.
    auto issue = [&](int t) {
        const int s  = t & 1;
        const uint32_t sb = smb + s * STAGE_BYTES;
        const int k0 = t * 32;
        #pragma unroll
        for (int i = 0; i < 2; ++i) {
            int ch = tid + i * 256;       // 0..511
            int m = ch >> 2, c = ch & 3;
            // ---- A ----
            int r = brow + m;
            uint32_t sz = (r < M) ? 16u : 0u;
            int rc = (r < M) ? r : (M - 1);
            const __half *pH, *pL;
            if (!CONCAT || k0 < IN_FEAT) {
                size_t o = (size_t)rc * IN_FEAT + k0 + c * 8;
                pH = A0h + o; pL = A0l + o;
            } else {
                size_t o = (size_t)rc * HID + (k0 - IN_FEAT) + c * 8;
                pH = A1h + o; pL = A1l + o;
            }
            uint32_t da = sb + (uint32_t)(m * 20 + c * 4) * 4;
            CP_ASYNC16(da,          pH, sz);
            CP_ASYNC16(da + 10240,  pL, sz);
            // ---- B ----
            int n = bcol + m;
            size_t ob = (size_t)n * KTOT + k0 + c * 8;
            CP_ASYNC16(da + 20480, Bh + ob, 16u);
            CP_ASYNC16(da + 30720, Bl + ob, 16u);
        }
    };

    issue(0); CP_COMMIT();
    if (T > 1) issue(1);
    CP_COMMIT();

    for (int t = 0; t < T; ++t) {
        CP_WAIT1();
        __syncthreads();

        const uint32_t* Ash = sm + (t & 1) * (STAGE_BYTES / 4);
        const uint32_t* Asl = Ash + 2560;
        const uint32_t* Bsh = Ash + 5120;
        const uint32_t* Bsl = Ash + 7680;

        #pragma unroll
        for (int ks2 = 0; ks2 < 2; ++ks2) {     // two K=16 steps per 32-k tile
            const int kb = ks2 * 8;             // pair offset
            uint32_t afh[2][4], afl[2][4];
            #pragma unroll
            for (int mt = 0; mt < 2; ++mt) {
                int m0 = wm * 32 + mt * 16 + g;
                int o00 = m0 * 20 + kb + tg;
                int o10 = (m0 + 8) * 20 + kb + tg;
                afh[mt][0] = Ash[o00];     afl[mt][0] = Asl[o00];
                afh[mt][1] = Ash[o10];     afl[mt][1] = Asl[o10];
                afh[mt][2] = Ash[o00 + 4]; afl[mt][2] = Asl[o00 + 4];
                afh[mt][3] = Ash[o10 + 4]; afl[mt][3] = Asl[o10 + 4];
            }
            #pragma unroll
            for (int nt = 0; nt < 8; ++nt) {
                int n = wn * 64 + nt * 8 + g;
                int ob = n * 20 + kb + tg;
                uint32_t bh0 = Bsh[ob], bh1 = Bsh[ob + 4];
                uint32_t bl0 = Bsl[ob], bl1 = Bsl[ob + 4];
                #pragma unroll
                for (int mt = 0; mt < 2; ++mt) {
                    MMA_F16(acc[mt][nt], afh[mt], bh0, bh1);
                    MMA_F16(acc[mt][nt], afl[mt], bh0, bh1);
                    MMA_F16(acc[mt][nt], afh[mt], bl0, bl1);
                }
            }
        }
        __syncthreads();
        if (t + 2 < T) issue(t + 2);
        CP_COMMIT();
    }

    // ---- epilogue ----
    #pragma unroll
    for (int mt = 0; mt < 2; ++mt) {
        int row0 = brow + wm * 32 + mt * 16 + g;
        int row1 = row0 + 8;
        #pragma unroll
        for (int nt = 0; nt < 8; ++nt) {
            int col = bcol + wn * 64 + nt * 8 + tg * 2;
            float b0 = BIAS ? bias[col]     : 0.f;
            float b1 = BIAS ? bias[col + 1] : 0.f;
            if (row0 < M) {
                float2 o = make_float2(acc[mt][nt][0] + b0, acc[mt][nt][1] + b1);
                *(float2*)(C + (size_t)row0 * NOUT + col) = o;
            }
            if (row1 < M) {
                float2 o = make_float2(acc[mt][nt][2] + b0, acc[mt][nt][3] + b1);
                *(float2*)(C + (size_t)row1 * NOUT + col) = o;
            }
        }
    }
}

// ---------------------------------------------------------------------------
// launch
// ---------------------------------------------------------------------------
extern "C" void kernel_launch(void* const* d_in, const int* in_sizes, int n_in,
                              void* d_out, int out_size) {
    const float* x   = (const float*)d_in[0];
    const float* w   = (const float*)d_in[1];
    const int*   src = (const int*)  d_in[2];
    const int*   dst = (const int*)  d_in[3];
    const float* Wn  = (const float*)d_in[4];
    const float* bn  = (const float*)d_in[5];
    const float* We  = (const float*)d_in[6];
    const float* be  = (const float*)d_in[7];
    const float* Wm  = (const float*)d_in[8];
    const float* bm  = (const float*)d_in[9];
    float*       out = (float*)d_out;

    float *y, *cvec;
    __half *xh, *xl, *mh, *ml, *Bth, *Btl, *Weth, *Wetl;
    cudaGetSymbolAddress((void**)&y,    g_y);
    cudaGetSymbolAddress((void**)&cvec, g_c);
    cudaGetSymbolAddress((void**)&xh,   g_xh);
    cudaGetSymbolAddress((void**)&xl,   g_xl);
    cudaGetSymbolAddress((void**)&mh,   g_mh);
    cudaGetSymbolAddress((void**)&ml,   g_ml);
    cudaGetSymbolAddress((void**)&Bth,  g_Bth);
    cudaGetSymbolAddress((void**)&Btl,  g_Btl);
    cudaGetSymbolAddress((void**)&Weth, g_Weth);
    cudaGetSymbolAddress((void**)&Wetl, g_Wetl);

    cudaFuncSetAttribute(gemm_f16_kernel<IN_FEAT, HID, false, false>,
                         cudaFuncAttributeMaxDynamicSharedMemorySize, GEMM_SMEM);
    cudaFuncSetAttribute(gemm_f16_kernel<K_FINAL, OUT_FEAT, true, true>,
                         cudaFuncAttributeMaxDynamicSharedMemorySize, GEMM_SMEM);

    // CSR build
    zero_cnt_kernel<<<(N_NODES + 255) / 256, 256>>>();
    hist_kernel<<<(N_EDGES + 255) / 256, 256>>>(dst);
    scan_kernel<<<1, 1024>>>();
    scatter_kernel<<<(N_EDGES + 255) / 256, 256>>>(src, dst, w);

    // pre-split x; fold weights
    split_x_kernel<<<(N_NODES * IN_FEAT / 4 + 255) / 256, 256>>>((const float4*)x);
    fold_b2t_kernel<<<OUT_FEAT, K_FINAL>>>(Wn, bn, be, Wm, bm);
    fold_wet_kernel<<<(IN_FEAT * HID + 255) / 256, 256>>>(We);

    // y = x @ W_edge   [50000 x 128] fp32
    {
        dim3 grid(1, (N_NODES + 127) / 128);
        gemm_f16_kernel<IN_FEAT, HID, false, false>
            <<<grid, 256, GEMM_SMEM>>>(xh, xl, nullptr, nullptr,
                                       Weth, Wetl, nullptr, y, N_NODES);
    }

    // msg aggregation (CSR, no atomics) -> split fp16
    agg_csr_kernel<<<(N_NODES * 32 + 255) / 256, 256>>>();

    // out = [x | msg] @ B2 + c   [50000 x 256]
    {
        dim3 grid(OUT_FEAT / 128, (N_NODES + 127) / 128);
        gemm_f16_kernel<K_FINAL, OUT_FEAT, true, true>
            <<<grid, 256, GEMM_SMEM>>>(xh, xl, mh, ml,
                                       Bth, Btl, cvec, out, N_NODES);
    }
}